// round 9
// baseline (speedup 1.0000x reference)
#include <cuda_runtime.h>
#include <cuda_bf16.h>
#include <cfloat>
#include <cmath>

#define BB 32
#define NN 256
#define LL 50
#define BN (BB * NN)          // 8192
#define DU 32
#define DI 32
#define DC 16
#define DD 48
#define FEAT 128

// ---------------- scratch (no allocs allowed) ----------------
__device__ float g_feat[BN * FEAT];
__device__ float g_logits[BN];
__device__ __align__(16) float g_WbcT[64 * 48];  // [j][k] = w1b - w1c
__device__ __align__(16) float g_WacT[64 * 48];  // [j][k] = w1a + w1c
__device__ __align__(16) float g_WdT [64 * 48];  // [j][k] = w1d
__device__ float g_v[64];                        // w2 @ w3
__device__ float g_cs[1];                        // b2.w3 + b3

// ---------------- helpers ----------------
__device__ __forceinline__ void ffma2(unsigned long long& acc,
                                      unsigned long long a,
                                      unsigned long long b) {
    asm("fma.rn.f32x2 %0, %1, %2, %0;" : "+l"(acc) : "l"(a), "l"(b));
}
__device__ __forceinline__ void upk(unsigned long long v, float& x, float& y) {
    asm("mov.b64 {%0,%1}, %2;" : "=f"(x), "=f"(y) : "l"(v));
}
__device__ __forceinline__ unsigned long long pk(float x, float y) {
    unsigned long long r;
    asm("mov.b64 %0, {%1,%2};" : "=l"(r) : "f"(x), "f"(y));
    return r;
}
__device__ __forceinline__ unsigned sptr(const void* p) {
    return (unsigned)__cvta_generic_to_shared(p);
}
__device__ __forceinline__ void lds_v2u64(unsigned addr,
                                          unsigned long long& a,
                                          unsigned long long& b) {
    asm("ld.shared.v2.u64 {%0,%1}, [%2];" : "=l"(a), "=l"(b) : "r"(addr));
}
__device__ __forceinline__ void sts_u64(unsigned addr, unsigned long long v) {
    asm("st.shared.u64 [%0], %1;" :: "r"(addr), "l"(v));
}
__device__ __forceinline__ void cpasync16(unsigned dst, const void* src) {
    asm volatile("cp.async.ca.shared.global [%0], [%1], 16;"
                 :: "r"(dst), "l"(src));
}
__device__ __forceinline__ void cpasync_wait_all() {
    asm volatile("cp.async.commit_group;\ncp.async.wait_group 0;" ::: "memory");
}

// ---------------- K0: fold attention weights ----------------
__global__ void setup_kernel(const float* __restrict__ w1,
                             const float* __restrict__ w2,
                             const float* __restrict__ w3,
                             const float* __restrict__ b2,
                             const float* __restrict__ b3)
{
    int e = blockIdx.x * 256 + threadIdx.x;
    if (blockIdx.x < 12) {
        int j = e / 48, k = e % 48;
        float a = w1[k * 64 + j];
        float b = w1[(48 + k) * 64 + j];
        float c = w1[(96 + k) * 64 + j];
        float d = w1[(144 + k) * 64 + j];
        g_WbcT[j * 48 + k] = b - c;
        g_WacT[j * 48 + k] = a + c;
        g_WdT [j * 48 + k] = d;
    } else {
        int t = threadIdx.x;
        if (t < 64) {
            float v = 0.f;
#pragma unroll
            for (int m = 0; m < 16; m++) v += w2[t * 16 + m] * w3[m];
            g_v[t] = v;
        } else if (t == 64) {
            float cs = b3[0];
#pragma unroll
            for (int m = 0; m < 16; m++) cs += b2[m] * w3[m];
            g_cs[0] = cs;
        }
    }
}

// ---------------- K1: attention (round-6 best variant) ----------------
__global__ void __launch_bounds__(128, 4) attn_kernel(
    const float* __restrict__ emb_user,
    const float* __restrict__ emb_item,
    const float* __restrict__ emb_cate,
    const float* __restrict__ b1,
    const int* __restrict__ user,
    const int* __restrict__ items,
    const int* __restrict__ items_cate,
    const int* __restrict__ ii,
    const int* __restrict__ iic)
{
    const int bn    = blockIdx.x;
    const int t     = threadIdx.x;
    const int w     = t >> 5;
    const int lane  = t & 31;
    const int jq    = lane & 15;
    const int khalf = lane >> 4;

    __shared__ __align__(16) float q_s[48];
    __shared__ __align__(16) unsigned long long Mx[24 * 64]; // [kp][j]
    __shared__ float cn_part[2][64];
    __shared__ float v_s[64];
    __shared__ __align__(16) float he_s[LL][52];
    __shared__ float S[LL][17];
    __shared__ float sc_s[LL];
    __shared__ int   idx_s[LL];

    // ================= phase 1 ============================================
    {
        const unsigned heb = sptr(he_s);
#pragma unroll
        for (int u = 0; u < 5; u++) {
            int idx = t + u * 128;
            if (idx < LL * 12) {
                int row = idx / 12, c = idx % 12;
                const float* src;
                if (c < 8) {
                    int e = __ldg(&ii[bn * LL + row]);
                    src = emb_item + (size_t)e * DI + c * 4;
                } else {
                    int e = __ldg(&iic[bn * LL + row]);
                    src = emb_cate + (size_t)e * DC + (c - 8) * 4;
                }
                cpasync16(heb + row * 208 + c * 16, src);
            }
        }
    }

    {
        const int it = __ldg(&items[bn]);
        const int ic = __ldg(&items_cate[bn]);
        if (t < 32)       q_s[t] = __ldg(&emb_item[(size_t)it * DI + t]);
        else if (t < 48)  q_s[t] = __ldg(&emb_cate[(size_t)ic * DC + (t - 32)]);
        if (t < 64)       v_s[t] = g_v[t];
        if (t >= 64 && t < 64 + LL) idx_s[t - 64] = __ldg(&ii[bn * LL + (t - 64)]);
    }

    {
        const int j = t & 63;
        const int half = t >> 6;
        const int it = __ldg(&items[bn]);
        const int ic = __ldg(&items_cate[bn]);
        float cn = (half == 0) ? b1[j] : 0.f;
        const float4* wbc = (const float4*)(g_WbcT + j * 48) + half * 6;
        const float4* wac = (const float4*)(g_WacT + j * 48) + half * 6;
        const float4* wd  = (const float4*)(g_WdT  + j * 48) + half * 6;
        unsigned mxb = sptr(Mx) + j * 8 + half * 12 * 512;
#pragma unroll
        for (int c = 0; c < 6; c++) {
            int k4 = half * 24 + c * 4;
            float4 qb;
            if (k4 < 32) qb = *(const float4*)(emb_item + (size_t)it * DI + k4);
            else         qb = *(const float4*)(emb_cate + (size_t)ic * DC + (k4 - 32));
            float4 fb = wbc[c], fa = wac[c], fd = wd[c];
            float mx = fmaf(qb.x, fd.x, fb.x);
            float my = fmaf(qb.y, fd.y, fb.y);
            float mz = fmaf(qb.z, fd.z, fb.z);
            float mw = fmaf(qb.w, fd.w, fb.w);
            sts_u64(mxb + (2 * c) * 512, pk(mx, my));
            sts_u64(mxb + (2 * c + 1) * 512, pk(mz, mw));
            cn = fmaf(qb.x, fa.x, cn);
            cn = fmaf(qb.y, fa.y, cn);
            cn = fmaf(qb.z, fa.z, cn);
            cn = fmaf(qb.w, fa.w, cn);
        }
        cn_part[half][j] = cn;
    }
    cpasync_wait_all();
    __syncthreads();

    // ================= phase 2: score ======================================
    unsigned long long A0[12], A1[12], A2[12], A3[12];
    {
        unsigned mb = sptr(Mx) + (4 * jq) * 8 + khalf * 12 * 512;
#pragma unroll
        for (int i = 0; i < 12; i++) {
            lds_v2u64(mb + i * 512,      A0[i], A1[i]);
            lds_v2u64(mb + i * 512 + 16, A2[i], A3[i]);
        }
    }
    const float cn0 = cn_part[0][4 * jq]     + cn_part[1][4 * jq];
    const float cn1 = cn_part[0][4 * jq + 1] + cn_part[1][4 * jq + 1];
    const float cn2 = cn_part[0][4 * jq + 2] + cn_part[1][4 * jq + 2];
    const float cn3 = cn_part[0][4 * jq + 3] + cn_part[1][4 * jq + 3];
    const float v0 = v_s[4 * jq],     v1 = v_s[4 * jq + 1];
    const float v2 = v_s[4 * jq + 2], v3 = v_s[4 * jq + 3];

    const int l0  = (w < 2) ? w * 13 : 26 + (w - 2) * 12;
    const int cnt = (w < 2) ? 13 : 12;
    for (int li = 0; li < cnt; li++) {
        const int l = l0 + li;
        unsigned hb = sptr(&he_s[l][0]) + khalf * 96;
        unsigned long long a0 = 0ull, a1 = 0ull, a2 = 0ull, a3 = 0ull;
#pragma unroll
        for (int c = 0; c < 6; c++) {
            unsigned long long h0, h1;
            lds_v2u64(hb + c * 16, h0, h1);
            ffma2(a0, h0, A0[2 * c]);
            ffma2(a0, h1, A0[2 * c + 1]);
            ffma2(a1, h0, A1[2 * c]);
            ffma2(a1, h1, A1[2 * c + 1]);
            ffma2(a2, h0, A2[2 * c]);
            ffma2(a2, h1, A2[2 * c + 1]);
            ffma2(a3, h0, A3[2 * c]);
            ffma2(a3, h1, A3[2 * c + 1]);
        }
        float x, y;
        upk(a0, x, y); float p0 = x + y;
        upk(a1, x, y); float p1 = x + y;
        upk(a2, x, y); float p2 = x + y;
        upk(a3, x, y); float p3 = x + y;
        p0 += __shfl_xor_sync(0xffffffffu, p0, 16);
        p1 += __shfl_xor_sync(0xffffffffu, p1, 16);
        p2 += __shfl_xor_sync(0xffffffffu, p2, 16);
        p3 += __shfl_xor_sync(0xffffffffu, p3, 16);
        float s;
        s  = fmaxf(p0 + cn0, 0.f) * v0;
        s  = fmaf(fmaxf(p1 + cn1, 0.f), v1, s);
        s  = fmaf(fmaxf(p2 + cn2, 0.f), v2, s);
        s  = fmaf(fmaxf(p3 + cn3, 0.f), v3, s);
        S[l][jq] = s;
    }
    __syncthreads();

    // ================= phase 3: score reduce ===============================
    if (t < LL) {
        float s = g_cs[0];
#pragma unroll
        for (int k = 0; k < 16; k++) s += S[t][k];
        sc_s[t] = (idx_s[t] == 0) ? 0.f : s;
    }
    __syncthreads();

    // ================= phase 4: pooled + feat ==============================
    float* fo = g_feat + bn * FEAT;
    if (t < 48) {
        float pooled = 0.f;
#pragma unroll 10
        for (int l = 0; l < LL; l++)
            pooled = fmaf(sc_s[l], he_s[l][t], pooled);
        fo[t]      = q_s[t];
        fo[48 + t] = pooled;
    } else if (t < 80) {
        fo[96 + (t - 48)] = __ldg(&emb_user[(size_t)__ldg(&user[bn]) * DU + (t - 48)]);
    }
}

// ---------------- K2: FC MLP, balanced register tile ----------------
#define ROWS 16
__global__ void __launch_bounds__(256) fc_kernel(
    const float* __restrict__ fw1, const float* __restrict__ fb1,
    const float* __restrict__ fw2, const float* __restrict__ fb2,
    const float* __restrict__ fw3, const float* __restrict__ fb3)
{
    const int t = threadIdx.x;
    const int row0 = blockIdx.x * ROWS;

    __shared__ __align__(16) float fs[ROWS][132];
    __shared__ __align__(16) float x1[ROWS][204];
    __shared__ __align__(16) float x2[ROWS][84];

    const float4* src = (const float4*)(g_feat + row0 * FEAT);
    for (int i = t; i < ROWS * FEAT / 4; i += 256) {
        float4 v = src[i];
        int r = i >> 5, c = (i & 31) * 4;
        fs[r][c] = v.x; fs[r][c + 1] = v.y;
        fs[r][c + 2] = v.z; fs[r][c + 3] = v.w;
    }
    __syncthreads();

    if (t < 200) {
        const int jjq = t % 50;
        const int rg  = (t / 50) * 4;
        const float* wbase = fw1 + 4 * jjq;
        const unsigned long long b0 = pk(fb1[4 * jjq],     fb1[4 * jjq + 1]);
        const unsigned long long b1v = pk(fb1[4 * jjq + 2], fb1[4 * jjq + 3]);
        unsigned long long acc[4][2];
#pragma unroll
        for (int r = 0; r < 4; r++) { acc[r][0] = b0; acc[r][1] = b1v; }
#pragma unroll 4
        for (int i = 0; i < FEAT; i++) {
            float4 wv = __ldg((const float4*)(wbase + i * 200));
            unsigned long long wp0 = pk(wv.x, wv.y);
            unsigned long long wp1 = pk(wv.z, wv.w);
#pragma unroll
            for (int r = 0; r < 4; r++) {
                float xv = fs[rg + r][i];
                unsigned long long xx = pk(xv, xv);
                ffma2(acc[r][0], xx, wp0);
                ffma2(acc[r][1], xx, wp1);
            }
        }
#pragma unroll
        for (int r = 0; r < 4; r++) {
            float h0, h1, h2, h3;
            upk(acc[r][0], h0, h1);
            upk(acc[r][1], h2, h3);
            float4 o;
            o.x = fmaxf(h0, 0.f); o.y = fmaxf(h1, 0.f);
            o.z = fmaxf(h2, 0.f); o.w = fmaxf(h3, 0.f);
            *(float4*)&x1[rg + r][4 * jjq] = o;
        }
    }
    __syncthreads();

    if (t < 160) {
        const int jjq = t % 20;
        const int rg  = (t / 20) * 2;
        const float* wbase = fw2 + 4 * jjq;
        const unsigned long long b0 = pk(fb2[4 * jjq],     fb2[4 * jjq + 1]);
        const unsigned long long b1v = pk(fb2[4 * jjq + 2], fb2[4 * jjq + 3]);
        unsigned long long acc[2][2];
#pragma unroll
        for (int r = 0; r < 2; r++) { acc[r][0] = b0; acc[r][1] = b1v; }
#pragma unroll 4
        for (int i = 0; i < 200; i++) {
            float4 wv = __ldg((const float4*)(wbase + i * 80));
            unsigned long long wp0 = pk(wv.x, wv.y);
            unsigned long long wp1 = pk(wv.z, wv.w);
#pragma unroll
            for (int r = 0; r < 2; r++) {
                float xv = x1[rg + r][i];
                unsigned long long xx = pk(xv, xv);
                ffma2(acc[r][0], xx, wp0);
                ffma2(acc[r][1], xx, wp1);
            }
        }
#pragma unroll
        for (int r = 0; r < 2; r++) {
            float h0, h1, h2, h3;
            upk(acc[r][0], h0, h1);
            upk(acc[r][1], h2, h3);
            float4 o;
            o.x = fmaxf(h0, 0.f); o.y = fmaxf(h1, 0.f);
            o.z = fmaxf(h2, 0.f); o.w = fmaxf(h3, 0.f);
            *(float4*)&x2[rg + r][4 * jjq] = o;
        }
    }
    __syncthreads();

    if (t < ROWS) {
        const unsigned long long* wp = (const unsigned long long*)fw3;
        const unsigned long long* xp = (const unsigned long long*)&x2[t][0];
        unsigned long long acc = 0ull;
#pragma unroll
        for (int ip = 0; ip < 40; ip++)
            ffma2(acc, xp[ip], __ldg(&wp[ip]));
        float a, b;
        upk(acc, a, b);
        float s = a + b + fb3[0];
        g_logits[row0 + t] = 1.0f / (1.0f + expf(-s));
    }
}

// ---------------- K3: masked softmax ----------------
__global__ void __launch_bounds__(256) softmax_kernel(
    const int* __restrict__ items, float* __restrict__ out)
{
    const int b = blockIdx.x;
    const int t = threadIdx.x;
    const int wid = t >> 5, lane = t & 31;

    __shared__ float red[8];
    __shared__ float s_mx, s_sum;

    float l = g_logits[b * NN + t];
    bool masked = (items[b * NN + t] == 0);
    float val = masked ? -FLT_MAX : l;

    float mx = val;
#pragma unroll
    for (int o = 16; o > 0; o >>= 1)
        mx = fmaxf(mx, __shfl_down_sync(0xffffffffu, mx, o));
    if (lane == 0) red[wid] = mx;
    __syncthreads();
    if (t == 0) {
        float m = red[0];
#pragma unroll
        for (int w = 1; w < 8; w++) m = fmaxf(m, red[w]);
        s_mx = m;
    }
    __syncthreads();
    float m = s_mx;

    float e = masked ? 0.0f : expf(l - m);
    float sum = e;
#pragma unroll
    for (int o = 16; o > 0; o >>= 1)
        sum += __shfl_down_sync(0xffffffffu, sum, o);
    if (lane == 0) red[wid] = sum;
    __syncthreads();
    if (t == 0) {
        float s = 0.0f;
#pragma unroll
        for (int w = 0; w < 8; w++) s += red[w];
        s_sum = s;
    }
    __syncthreads();

    out[b * NN + t] = e / s_sum;
}

// ---------------- launch ----------------
// MEASUREMENT ROUND: attn launched 4x (idempotent — writes identical g_feat).
// T_attn = (total - 167.0) / 3. Output unchanged.
extern "C" void kernel_launch(void* const* d_in, const int* in_sizes, int n_in,
                              void* d_out, int out_size)
{
    const float* emb_user  = (const float*)d_in[0];
    const float* emb_item  = (const float*)d_in[1];
    const float* emb_cate  = (const float*)d_in[2];
    const float* att_w1    = (const float*)d_in[3];
    const float* att_b1    = (const float*)d_in[4];
    const float* att_w2    = (const float*)d_in[5];
    const float* att_b2    = (const float*)d_in[6];
    const float* att_w3    = (const float*)d_in[7];
    const float* att_b3    = (const float*)d_in[8];
    const float* fc_w1     = (const float*)d_in[9];
    const float* fc_b1     = (const float*)d_in[10];
    const float* fc_w2     = (const float*)d_in[11];
    const float* fc_b2     = (const float*)d_in[12];
    const float* fc_w3     = (const float*)d_in[13];
    const float* fc_b3     = (const float*)d_in[14];
    const int*   user      = (const int*)d_in[15];
    const int*   items     = (const int*)d_in[16];
    const int*   items_cate= (const int*)d_in[17];
    const int*   ii        = (const int*)d_in[18];
    const int*   iic       = (const int*)d_in[19];
    float* out = (float*)d_out;

    setup_kernel<<<13, 256>>>(att_w1, att_w2, att_w3, att_b2, att_b3);
    attn_kernel<<<BN, 128>>>(emb_user, emb_item, emb_cate, att_b1,
                             user, items, items_cate, ii, iic);
    attn_kernel<<<BN, 128>>>(emb_user, emb_item, emb_cate, att_b1,
                             user, items, items_cate, ii, iic);
    attn_kernel<<<BN, 128>>>(emb_user, emb_item, emb_cate, att_b1,
                             user, items, items_cate, ii, iic);
    attn_kernel<<<BN, 128>>>(emb_user, emb_item, emb_cate, att_b1,
                             user, items, items_cate, ii, iic);
    fc_kernel<<<BN / ROWS, 256>>>(fc_w1, fc_b1, fc_w2, fc_b2, fc_w3, fc_b3);
    softmax_kernel<<<BB, 256>>>(items, out);
}

// round 10
// speedup vs baseline: 3.9602x; 3.9602x over previous
#include <cuda_runtime.h>
#include <cuda_bf16.h>
#include <cfloat>
#include <cmath>

#define BB 32
#define NN 256
#define LL 50
#define BN (BB * NN)          // 8192
#define DU 32
#define DI 32
#define DC 16
#define DD 48
#define FEAT 128

// ---------------- scratch (no allocs allowed) ----------------
__device__ float g_feat[BN * FEAT];
__device__ float g_logits[BN];
// packed k-pair-major folded-weight layouts: [kp][j], kp=0..23, j=0..63
__device__ __align__(16) unsigned long long g_Wbc2[24 * 64]; // (b-c) pairs
__device__ __align__(16) unsigned long long g_Wac2[24 * 64]; // (a+c) pairs
__device__ __align__(16) unsigned long long g_Wd2 [24 * 64]; // d pairs
__device__ float g_v[64];                        // w2 @ w3
__device__ float g_cs[1];                        // b2.w3 + b3

// ---------------- helpers ----------------
__device__ __forceinline__ void ffma2(unsigned long long& acc,
                                      unsigned long long a,
                                      unsigned long long b) {
    asm("fma.rn.f32x2 %0, %1, %2, %0;" : "+l"(acc) : "l"(a), "l"(b));
}
__device__ __forceinline__ void upk(unsigned long long v, float& x, float& y) {
    asm("mov.b64 {%0,%1}, %2;" : "=f"(x), "=f"(y) : "l"(v));
}
__device__ __forceinline__ unsigned long long pk(float x, float y) {
    unsigned long long r;
    asm("mov.b64 %0, {%1,%2};" : "=l"(r) : "f"(x), "f"(y));
    return r;
}
__device__ __forceinline__ unsigned sptr(const void* p) {
    return (unsigned)__cvta_generic_to_shared(p);
}
__device__ __forceinline__ void lds_v2u64(unsigned addr,
                                          unsigned long long& a,
                                          unsigned long long& b) {
    asm("ld.shared.v2.u64 {%0,%1}, [%2];" : "=l"(a), "=l"(b) : "r"(addr));
}
__device__ __forceinline__ void sts_u64(unsigned addr, unsigned long long v) {
    asm("st.shared.u64 [%0], %1;" :: "r"(addr), "l"(v));
}
__device__ __forceinline__ void cpasync16(unsigned dst, const void* src) {
    asm volatile("cp.async.ca.shared.global [%0], [%1], 16;"
                 :: "r"(dst), "l"(src));
}
__device__ __forceinline__ void cpasync_wait_all() {
    asm volatile("cp.async.commit_group;\ncp.async.wait_group 0;" ::: "memory");
}

// ---------------- K0: fold attention weights into packed pair layout ------
__global__ void setup_kernel(const float* __restrict__ w1,
                             const float* __restrict__ w2,
                             const float* __restrict__ w3,
                             const float* __restrict__ b2,
                             const float* __restrict__ b3)
{
    int e = blockIdx.x * 256 + threadIdx.x;
    if (blockIdx.x < 6) {           // 1536 elements: (kp, j)
        int kp = e / 64, j = e % 64;
        int k0 = 2 * kp, k1 = 2 * kp + 1;
        float a0 = w1[k0 * 64 + j];
        float b0 = w1[(48 + k0) * 64 + j];
        float c0 = w1[(96 + k0) * 64 + j];
        float d0 = w1[(144 + k0) * 64 + j];
        float a1 = w1[k1 * 64 + j];
        float bb1 = w1[(48 + k1) * 64 + j];
        float c1 = w1[(96 + k1) * 64 + j];
        float d1 = w1[(144 + k1) * 64 + j];
        g_Wbc2[e] = pk(b0 - c0, bb1 - c1);
        g_Wac2[e] = pk(a0 + c0, a1 + c1);
        g_Wd2[e]  = pk(d0, d1);
    } else {
        int t = threadIdx.x;
        if (t < 64) {
            float v = 0.f;
#pragma unroll
            for (int m = 0; m < 16; m++) v += w2[t * 16 + m] * w3[m];
            g_v[t] = v;
        } else if (t == 64) {
            float cs = b3[0];
#pragma unroll
            for (int m = 0; m < 16; m++) cs += b2[m] * w3[m];
            g_cs[0] = cs;
        }
    }
}

// ---------------- K1: attention ----------------
__global__ void __launch_bounds__(128, 4) attn_kernel(
    const float* __restrict__ emb_user,
    const float* __restrict__ emb_item,
    const float* __restrict__ emb_cate,
    const float* __restrict__ b1,
    const int* __restrict__ user,
    const int* __restrict__ items,
    const int* __restrict__ items_cate,
    const int* __restrict__ ii,
    const int* __restrict__ iic)
{
    const int bn    = blockIdx.x;
    const int t     = threadIdx.x;
    const int w     = t >> 5;
    const int lane  = t & 31;
    const int jq    = lane & 15;
    const int khalf = lane >> 4;

    __shared__ __align__(16) float q_s[48];
    __shared__ __align__(16) unsigned long long Mx[24 * 64]; // [kp][j]
    __shared__ float cn_part[2][64];
    __shared__ float v_s[64];
    __shared__ __align__(16) float he_s[LL][52];
    __shared__ float S[LL][17];
    __shared__ float sc_s[LL];
    __shared__ int   idx_s[LL];

    // ================= phase 1 (no barrier until cp.async wait) ==========
    // (a) he gathers via cp.async
    {
        const unsigned heb = sptr(he_s);
#pragma unroll
        for (int u = 0; u < 5; u++) {
            int idx = t + u * 128;
            if (idx < LL * 12) {
                int row = idx / 12, c = idx % 12;
                const float* src;
                if (c < 8) {
                    int e = __ldg(&ii[bn * LL + row]);
                    src = emb_item + (size_t)e * DI + c * 4;
                } else {
                    int e = __ldg(&iic[bn * LL + row]);
                    src = emb_cate + (size_t)e * DC + (c - 8) * 4;
                }
                cpasync16(heb + row * 208 + c * 16, src);
            }
        }
    }

    // (b) stage q (for feat output), v, mask indices
    {
        const int it = __ldg(&items[bn]);
        const int ic = __ldg(&items_cate[bn]);
        if (t < 32)       q_s[t] = __ldg(&emb_item[(size_t)it * DI + t]);
        else if (t < 48)  q_s[t] = __ldg(&emb_cate[(size_t)ic * DC + (t - 32)]);
        if (t < 64)       v_s[t] = g_v[t];
        if (t >= 64 && t < 64 + LL) idx_s[t - 64] = __ldg(&ii[bn * LL + (t - 64)]);
    }

    // (c) fold (coalesced): j = t&63, k-half = t>>6.
    //     M pair = Wbc2 + qpair * Wd2 ; cn accumulates qpair * Wac2.
    //     q pairs read from global (broadcast LDG.64) — no barrier needed.
    {
        const int j = t & 63;
        const int half = t >> 6;
        const int it = __ldg(&items[bn]);
        const int ic = __ldg(&items_cate[bn]);
        const unsigned long long* qitem =
            (const unsigned long long*)(emb_item + (size_t)it * DI);
        const unsigned long long* qcate =
            (const unsigned long long*)(emb_cate + (size_t)ic * DC);
        const unsigned long long* wbcp = g_Wbc2 + half * 12 * 64 + j;
        const unsigned long long* wacp = g_Wac2 + half * 12 * 64 + j;
        const unsigned long long* wdp  = g_Wd2  + half * 12 * 64 + j;
        unsigned mxb = sptr(Mx) + j * 8 + half * 12 * 512;
        unsigned long long cnacc = 0ull;
#pragma unroll
        for (int kp = 0; kp < 12; kp++) {
            const int kpg = half * 12 + kp;            // global pair idx
            unsigned long long qp = (kpg < 16) ? __ldg(&qitem[kpg])
                                               : __ldg(&qcate[kpg - 16]);
            unsigned long long m = __ldg(&wbcp[kp * 64]);
            ffma2(m, qp, __ldg(&wdp[kp * 64]));
            sts_u64(mxb + kp * 512, m);
            ffma2(cnacc, qp, __ldg(&wacp[kp * 64]));
        }
        float cx, cy;
        upk(cnacc, cx, cy);
        cn_part[half][j] = cx + cy + ((half == 0) ? b1[j] : 0.f);
    }
    cpasync_wait_all();
    __syncthreads();

    // ================= phase 2: score ======================================
    // A-tile: 4 columns (j = 4jq..4jq+3), my 24 k values = 48 u64.
    unsigned long long A0[12], A1[12], A2[12], A3[12];
    {
        unsigned mb = sptr(Mx) + (4 * jq) * 8 + khalf * 12 * 512;
#pragma unroll
        for (int i = 0; i < 12; i++) {
            lds_v2u64(mb + i * 512,      A0[i], A1[i]);
            lds_v2u64(mb + i * 512 + 16, A2[i], A3[i]);
        }
    }
    const float cn0 = cn_part[0][4 * jq]     + cn_part[1][4 * jq];
    const float cn1 = cn_part[0][4 * jq + 1] + cn_part[1][4 * jq + 1];
    const float cn2 = cn_part[0][4 * jq + 2] + cn_part[1][4 * jq + 2];
    const float cn3 = cn_part[0][4 * jq + 3] + cn_part[1][4 * jq + 3];
    const float v0 = v_s[4 * jq],     v1 = v_s[4 * jq + 1];
    const float v2 = v_s[4 * jq + 2], v3 = v_s[4 * jq + 3];

    const int l0  = (w < 2) ? w * 13 : 26 + (w - 2) * 12;
    const int cnt = (w < 2) ? 13 : 12;
    for (int li = 0; li < cnt; li++) {
        const int l = l0 + li;
        unsigned hb = sptr(&he_s[l][0]) + khalf * 96;
        unsigned long long a0 = 0ull, a1 = 0ull, a2 = 0ull, a3 = 0ull;
#pragma unroll
        for (int c = 0; c < 6; c++) {
            unsigned long long h0, h1;
            lds_v2u64(hb + c * 16, h0, h1);
            ffma2(a0, h0, A0[2 * c]);
            ffma2(a0, h1, A0[2 * c + 1]);
            ffma2(a1, h0, A1[2 * c]);
            ffma2(a1, h1, A1[2 * c + 1]);
            ffma2(a2, h0, A2[2 * c]);
            ffma2(a2, h1, A2[2 * c + 1]);
            ffma2(a3, h0, A3[2 * c]);
            ffma2(a3, h1, A3[2 * c + 1]);
        }
        float x, y;
        upk(a0, x, y); float p0 = x + y;
        upk(a1, x, y); float p1 = x + y;
        upk(a2, x, y); float p2 = x + y;
        upk(a3, x, y); float p3 = x + y;
        p0 += __shfl_xor_sync(0xffffffffu, p0, 16);
        p1 += __shfl_xor_sync(0xffffffffu, p1, 16);
        p2 += __shfl_xor_sync(0xffffffffu, p2, 16);
        p3 += __shfl_xor_sync(0xffffffffu, p3, 16);
        float s;
        s  = fmaxf(p0 + cn0, 0.f) * v0;
        s  = fmaf(fmaxf(p1 + cn1, 0.f), v1, s);
        s  = fmaf(fmaxf(p2 + cn2, 0.f), v2, s);
        s  = fmaf(fmaxf(p3 + cn3, 0.f), v3, s);
        S[l][jq] = s;
    }
    __syncthreads();

    // ================= phase 3: score reduce ===============================
    if (t < LL) {
        float s = g_cs[0];
#pragma unroll
        for (int k = 0; k < 16; k++) s += S[t][k];
        sc_s[t] = (idx_s[t] == 0) ? 0.f : s;
    }
    __syncthreads();

    // ================= phase 4: pooled + feat ==============================
    float* fo = g_feat + bn * FEAT;
    if (t < 48) {
        float pooled = 0.f;
#pragma unroll 10
        for (int l = 0; l < LL; l++)
            pooled = fmaf(sc_s[l], he_s[l][t], pooled);
        fo[t]      = q_s[t];
        fo[48 + t] = pooled;
    } else if (t < 80) {
        fo[96 + (t - 48)] = __ldg(&emb_user[(size_t)__ldg(&user[bn]) * DU + (t - 48)]);
    }
}

// ---------------- K2: FC MLP, balanced register tile ----------------
#define ROWS 16
__global__ void __launch_bounds__(256) fc_kernel(
    const float* __restrict__ fw1, const float* __restrict__ fb1,
    const float* __restrict__ fw2, const float* __restrict__ fb2,
    const float* __restrict__ fw3, const float* __restrict__ fb3)
{
    const int t = threadIdx.x;
    const int row0 = blockIdx.x * ROWS;

    __shared__ __align__(16) float fs[ROWS][132];
    __shared__ __align__(16) float x1[ROWS][204];
    __shared__ __align__(16) float x2[ROWS][84];

    const float4* src = (const float4*)(g_feat + row0 * FEAT);
    for (int i = t; i < ROWS * FEAT / 4; i += 256) {
        float4 v = src[i];
        int r = i >> 5, c = (i & 31) * 4;
        fs[r][c] = v.x; fs[r][c + 1] = v.y;
        fs[r][c + 2] = v.z; fs[r][c + 3] = v.w;
    }
    __syncthreads();

    if (t < 200) {
        const int jjq = t % 50;
        const int rg  = (t / 50) * 4;
        const float* wbase = fw1 + 4 * jjq;
        const unsigned long long b0 = pk(fb1[4 * jjq],     fb1[4 * jjq + 1]);
        const unsigned long long b1v = pk(fb1[4 * jjq + 2], fb1[4 * jjq + 3]);
        unsigned long long acc[4][2];
#pragma unroll
        for (int r = 0; r < 4; r++) { acc[r][0] = b0; acc[r][1] = b1v; }
#pragma unroll 4
        for (int i = 0; i < FEAT; i++) {
            float4 wv = __ldg((const float4*)(wbase + i * 200));
            unsigned long long wp0 = pk(wv.x, wv.y);
            unsigned long long wp1 = pk(wv.z, wv.w);
#pragma unroll
            for (int r = 0; r < 4; r++) {
                float xv = fs[rg + r][i];
                unsigned long long xx = pk(xv, xv);
                ffma2(acc[r][0], xx, wp0);
                ffma2(acc[r][1], xx, wp1);
            }
        }
#pragma unroll
        for (int r = 0; r < 4; r++) {
            float h0, h1, h2, h3;
            upk(acc[r][0], h0, h1);
            upk(acc[r][1], h2, h3);
            float4 o;
            o.x = fmaxf(h0, 0.f); o.y = fmaxf(h1, 0.f);
            o.z = fmaxf(h2, 0.f); o.w = fmaxf(h3, 0.f);
            *(float4*)&x1[rg + r][4 * jjq] = o;
        }
    }
    __syncthreads();

    if (t < 160) {
        const int jjq = t % 20;
        const int rg  = (t / 20) * 2;
        const float* wbase = fw2 + 4 * jjq;
        const unsigned long long b0 = pk(fb2[4 * jjq],     fb2[4 * jjq + 1]);
        const unsigned long long b1v = pk(fb2[4 * jjq + 2], fb2[4 * jjq + 3]);
        unsigned long long acc[2][2];
#pragma unroll
        for (int r = 0; r < 2; r++) { acc[r][0] = b0; acc[r][1] = b1v; }
#pragma unroll 4
        for (int i = 0; i < 200; i++) {
            float4 wv = __ldg((const float4*)(wbase + i * 80));
            unsigned long long wp0 = pk(wv.x, wv.y);
            unsigned long long wp1 = pk(wv.z, wv.w);
#pragma unroll
            for (int r = 0; r < 2; r++) {
                float xv = x1[rg + r][i];
                unsigned long long xx = pk(xv, xv);
                ffma2(acc[r][0], xx, wp0);
                ffma2(acc[r][1], xx, wp1);
            }
        }
#pragma unroll
        for (int r = 0; r < 2; r++) {
            float h0, h1, h2, h3;
            upk(acc[r][0], h0, h1);
            upk(acc[r][1], h2, h3);
            float4 o;
            o.x = fmaxf(h0, 0.f); o.y = fmaxf(h1, 0.f);
            o.z = fmaxf(h2, 0.f); o.w = fmaxf(h3, 0.f);
            *(float4*)&x2[rg + r][4 * jjq] = o;
        }
    }
    __syncthreads();

    if (t < ROWS) {
        const unsigned long long* wp = (const unsigned long long*)fw3;
        const unsigned long long* xp = (const unsigned long long*)&x2[t][0];
        unsigned long long acc = 0ull;
#pragma unroll
        for (int ip = 0; ip < 40; ip++)
            ffma2(acc, xp[ip], __ldg(&wp[ip]));
        float a, b;
        upk(acc, a, b);
        float s = a + b + fb3[0];
        g_logits[row0 + t] = 1.0f / (1.0f + expf(-s));
    }
}

// ---------------- K3: masked softmax ----------------
__global__ void __launch_bounds__(256) softmax_kernel(
    const int* __restrict__ items, float* __restrict__ out)
{
    const int b = blockIdx.x;
    const int t = threadIdx.x;
    const int wid = t >> 5, lane = t & 31;

    __shared__ float red[8];
    __shared__ float s_mx, s_sum;

    float l = g_logits[b * NN + t];
    bool masked = (items[b * NN + t] == 0);
    float val = masked ? -FLT_MAX : l;

    float mx = val;
#pragma unroll
    for (int o = 16; o > 0; o >>= 1)
        mx = fmaxf(mx, __shfl_down_sync(0xffffffffu, mx, o));
    if (lane == 0) red[wid] = mx;
    __syncthreads();
    if (t == 0) {
        float m = red[0];
#pragma unroll
        for (int w = 1; w < 8; w++) m = fmaxf(m, red[w]);
        s_mx = m;
    }
    __syncthreads();
    float m = s_mx;

    float e = masked ? 0.0f : expf(l - m);
    float sum = e;
#pragma unroll
    for (int o = 16; o > 0; o >>= 1)
        sum += __shfl_down_sync(0xffffffffu, sum, o);
    if (lane == 0) red[wid] = sum;
    __syncthreads();
    if (t == 0) {
        float s = 0.0f;
#pragma unroll
        for (int w = 0; w < 8; w++) s += red[w];
        s_sum = s;
    }
    __syncthreads();

    out[b * NN + t] = e / s_sum;
}

// ---------------- launch ----------------
extern "C" void kernel_launch(void* const* d_in, const int* in_sizes, int n_in,
                              void* d_out, int out_size)
{
    const float* emb_user  = (const float*)d_in[0];
    const float* emb_item  = (const float*)d_in[1];
    const float* emb_cate  = (const float*)d_in[2];
    const float* att_w1    = (const float*)d_in[3];
    const float* att_b1    = (const float*)d_in[4];
    const float* att_w2    = (const float*)d_in[5];
    const float* att_b2    = (const float*)d_in[6];
    const float* att_w3    = (const float*)d_in[7];
    const float* att_b3    = (const float*)d_in[8];
    const float* fc_w1     = (const float*)d_in[9];
    const float* fc_b1     = (const float*)d_in[10];
    const float* fc_w2     = (const float*)d_in[11];
    const float* fc_b2     = (const float*)d_in[12];
    const float* fc_w3     = (const float*)d_in[13];
    const float* fc_b3     = (const float*)d_in[14];
    const int*   user      = (const int*)d_in[15];
    const int*   items     = (const int*)d_in[16];
    const int*   items_cate= (const int*)d_in[17];
    const int*   ii        = (const int*)d_in[18];
    const int*   iic       = (const int*)d_in[19];
    float* out = (float*)d_out;

    setup_kernel<<<7, 256>>>(att_w1, att_w2, att_w3, att_b2, att_b3);
    attn_kernel<<<BN, 128>>>(emb_user, emb_item, emb_cate, att_b1,
                             user, items, items_cate, ii, iic);
    fc_kernel<<<BN / ROWS, 256>>>(fc_w1, fc_b1, fc_w2, fc_b2, fc_w3, fc_b3);
    softmax_kernel<<<BB, 256>>>(items, out);
}